// round 17
// baseline (speedup 1.0000x reference)
#include <cuda_runtime.h>
#include <cuda_bf16.h>
#include <mma.h>
#include <math.h>
#include <stdint.h>

using namespace nvcuda;

// ---------------------------------------------------------------------------
// QuanvolutionClassifier (sm_103a, HMMA path):
//   quanv+prep : circuit per patch -> feats bf16 hi/lo [b][KP];
//                extra blocks split W1 K-MAJOR [KP][128] (matches gemm!)
//   gemm       : 16-row tiles, 256 CTAs (2 CTAs/SM for cross-CTA overlap),
//                wmma bf16 split GEMM (AhBh + AhBl + AlBh, fp32 acc),
//                2-stage cp.async, split accumulators, fused epilogue.
// ---------------------------------------------------------------------------

#define MAX_B 4096
#define KP    832           // 784 padded (13*64)
#define NCH   13            // K chunks of 64

__device__ __align__(16) __nv_bfloat16 g_fh[MAX_B * KP];   // zero-init padding
__device__ __align__(16) __nv_bfloat16 g_fl[MAX_B * KP];
__device__ __align__(16) __nv_bfloat16 g_w1h[KP * 128];    // k-major [KP][128]
__device__ __align__(16) __nv_bfloat16 g_w1l[KP * 128];

// ========================= helpers =========================================
__device__ __forceinline__ uint32_t smem_u32(const void* p) {
    uint32_t a;
    asm("{ .reg .u64 t; cvta.to.shared.u64 t, %1; cvt.u32.u64 %0, t; }"
        : "=r"(a) : "l"(p));
    return a;
}
__device__ __forceinline__ void cp16(uint32_t dst, const void* src) {
    asm volatile("cp.async.cg.shared.global [%0], [%1], 16;"
                 :: "r"(dst), "l"(src) : "memory");
}
#define CP_COMMIT() asm volatile("cp.async.commit_group;" ::: "memory")
template <int N> __device__ __forceinline__ void cp_wait() {
    asm volatile("cp.async.wait_group %0;" :: "n"(N) : "memory");
}

// ===================== quanv + W1-split kernel =============================
// Blocks [0, qblocks): quanv.  Blocks [qblocks, +100): W1 k-major split.
__global__ __launch_bounds__(256) void quanv_kernel(
    const float* __restrict__ x, const float* __restrict__ theta,
    const float* __restrict__ W1, int B, int qblocks)
{
    if ((int)blockIdx.x >= qblocks) {
        // ---- W1 split, K-MAJOR: g_w1h/[KP][128], same layout as source.
        int idx = (blockIdx.x - qblocks) * 256 + threadIdx.x;  // 0..25599
        if (idx < 784 * 32) {
            float4 v = reinterpret_cast<const float4*>(W1)[idx];
            float vv[4] = {v.x, v.y, v.z, v.w};
            __nv_bfloat16 h[4], l[4];
#pragma unroll
            for (int j = 0; j < 4; j++) {
                h[j] = __float2bfloat16(vv[j]);
                l[j] = __float2bfloat16(vv[j] - __bfloat162float(h[j]));
            }
            reinterpret_cast<uint2*>(g_w1h)[idx] = *reinterpret_cast<uint2*>(h);
            reinterpret_cast<uint2*>(g_w1l)[idx] = *reinterpret_cast<uint2*>(l);
        }
        return;
    }

    __shared__ float2 sTrig[8];
    if (threadIdx.x < 8) {
        float c, s;
        __sincosf(0.5f * __ldg(&theta[threadIdx.x]), &s, &c);
        sTrig[threadIdx.x] = make_float2(c, s);
    }
    __syncthreads();

    int idx = blockIdx.x * blockDim.x + threadIdx.x;
    int total = B * 196;
    if (idx >= total) return;
    int b = idx / 196;
    int p = idx - b * 196;
    int r14 = p / 14;
    int c14 = p - r14 * 14;

    const float* xb = x + (size_t)b * 784 + (r14 * 2) * 28 + c14 * 2;
    float2 t0 = *reinterpret_cast<const float2*>(xb);
    float2 t1 = *reinterpret_cast<const float2*>(xb + 28);

    float c[4], s[4];
    __sincosf(0.5f * t0.x, &s[0], &c[0]);
    __sincosf(0.5f * t0.y, &s[1], &c[1]);
    __sincosf(0.5f * t1.x, &s[2], &c[2]);
    __sincosf(0.5f * t1.y, &s[3], &c[3]);

    float p01[4] = {c[0]*c[1], c[0]*s[1], s[0]*c[1], s[0]*s[1]};
    float p23[4] = {c[2]*c[3], c[2]*s[3], s[2]*c[3], s[2]*s[3]};
    float st[16];
#pragma unroll
    for (int i = 0; i < 16; i++) st[i] = p01[i >> 2] * p23[i & 3];

#pragma unroll
    for (int l = 0; l < 2; l++) {
#pragma unroll
        for (int w = 0; w < 4; w++) {
            float2 v = sTrig[l * 4 + w];
            float cc = v.x, ss = v.y;
            int mask = 8 >> w;
#pragma unroll
            for (int i = 0; i < 16; i++) {
                if (i & mask) continue;
                int j = i | mask;
                float a0 = st[i], a1 = st[j];
                st[i] = cc * a0 - ss * a1;
                st[j] = ss * a0 + cc * a1;
            }
        }
#pragma unroll
        for (int w = 0; w < 4; w++) {
            int cm = 8 >> w;
            int tm = 8 >> ((w + 1) & 3);
#pragma unroll
            for (int i = 0; i < 16; i++) {
                if ((i & cm) && !(i & tm)) {
                    int j = i | tm;
                    float tt = st[i]; st[i] = st[j]; st[j] = tt;
                }
            }
        }
    }

    float q[16];
#pragma unroll
    for (int i = 0; i < 16; i++) q[i] = st[i] * st[i];
    float o[4];
#pragma unroll
    for (int w = 0; w < 4; w++) {
        int mask = 8 >> w;
        float z = 0.f;
#pragma unroll
        for (int i = 0; i < 16; i++) z += (i & mask) ? -q[i] : q[i];
        o[w] = z;
    }

    __nv_bfloat16 h[4], l[4];
#pragma unroll
    for (int w = 0; w < 4; w++) {
        h[w] = __float2bfloat16(o[w]);
        l[w] = __float2bfloat16(o[w] - __bfloat162float(h[w]));
    }
    size_t off = (size_t)b * KP + p * 4;
    *reinterpret_cast<__nv_bfloat162*>(&g_fh[off])     = __nv_bfloat162(h[0], h[1]);
    *reinterpret_cast<__nv_bfloat162*>(&g_fh[off + 2]) = __nv_bfloat162(h[2], h[3]);
    *reinterpret_cast<__nv_bfloat162*>(&g_fl[off])     = __nv_bfloat162(l[0], l[1]);
    *reinterpret_cast<__nv_bfloat162*>(&g_fl[off + 2]) = __nv_bfloat162(l[2], l[3]);
}

// =============================== gemm kernel ===============================
// Grid = B/16 CTAs x 256 thr, 2 CTAs/SM. C[16x128] per CTA, K chunks of 64.
// A: [16][ASTR=72] bf16 (144B row). B: [k64][n128] bf16, BSTR=136 (272B row).
#define ASTR 72
#define A_HALF 2304                    // 16*144
#define A_SLOT (2 * A_HALF)            // Ah + Al = 4608
#define BSTR 136
#define B_HALF 17408                   // 64*272
#define B_SLOT (2 * B_HALF)            // 34816
#define STG_B  (A_SLOT + B_SLOT)       // 39424
#define DSMEM_B (2 * STG_B)            // 78848 per CTA (2 stages)
#define CSTR 132

__global__ __launch_bounds__(256, 2) void gemm_kernel(
    const __nv_bfloat16* __restrict__ fh, const __nv_bfloat16* __restrict__ fl,
    const __nv_bfloat16* __restrict__ wh, const __nv_bfloat16* __restrict__ wl,
    const float* __restrict__ b1, const float* __restrict__ W2,
    const float* __restrict__ b2, float* __restrict__ out, int B)
{
    extern __shared__ __align__(16) char db[];
    __shared__ float sW2t[1280];      // [q][128]
    __shared__ float sb1[128];

    int tid = threadIdx.x;
    int wid = tid >> 5;
    int lane = tid & 31;
    int row0 = blockIdx.x * 16;

    for (int i = tid; i < 1280; i += 256) {
        int qq = i >> 7, n = i & 127;
        sW2t[i] = W2[n * 10 + qq];
    }
    if (tid < 128) sb1[tid] = b1[tid];

    const uint4* fh4 = reinterpret_cast<const uint4*>(fh);
    const uint4* fl4 = reinterpret_cast<const uint4*>(fl);
    const uint4* wh4 = reinterpret_cast<const uint4*>(wh);
    const uint4* wl4 = reinterpret_cast<const uint4*>(wl);
    const int RSTR = KP / 8;          // 104 granules per feats row

    uint32_t sbase = smem_u32(db);

    // A: 256 granules/chunk (16 rows x 8 x {h,l}) -> 1 per thread
    int a_half = tid >> 7;            // 0=hi, 1=lo
    int ag = tid & 127;
    int a_r = ag >> 3, a_c = ag & 7;

    auto issue = [&](int kc, int slot) {
        uint32_t base = sbase + slot * STG_B;
        size_t oa = (size_t)(row0 + a_r) * RSTR + kc * 8 + a_c;
        cp16(base + a_half * A_HALF + a_r * 144 + a_c * 16,
             (a_half ? fl4 : fh4) + oa);
        // B (k-major [KP][128]): 64 rows x 16 granules x {h,l} -> 8 per thread
#pragma unroll
        for (int i = 0; i < 4; i++) {
            int gid = tid + i * 256;
            int r = gid >> 4, cc = gid & 15;
            size_t ob = (size_t)(kc * 64 + r) * 16 + cc;
            uint32_t dbb = base + A_SLOT + r * 272 + cc * 16;
            cp16(dbb, wh4 + ob);
            cp16(dbb + B_HALF, wl4 + ob);
        }
    };

    wmma::fragment<wmma::accumulator, 16, 16, 16, float> accH, accL;
    wmma::fill_fragment(accH, 0.f);
    wmma::fill_fragment(accL, 0.f);

    issue(0, 0); CP_COMMIT();
    issue(1, 1); CP_COMMIT();

    for (int i = 0; i < NCH; i++) {
        if (i == NCH - 1) cp_wait<0>(); else cp_wait<1>();
        __syncthreads();

        const __nv_bfloat16* sAh = reinterpret_cast<const __nv_bfloat16*>(
            db + (i & 1) * STG_B);
        const __nv_bfloat16* sAl = sAh + 16 * ASTR;
        const __nv_bfloat16* sBh = reinterpret_cast<const __nv_bfloat16*>(
            db + (i & 1) * STG_B + A_SLOT);
        const __nv_bfloat16* sBl = sBh + 64 * BSTR;

#pragma unroll
        for (int ks = 0; ks < 4; ks++) {
            wmma::fragment<wmma::matrix_a, 16, 16, 16, __nv_bfloat16, wmma::row_major> ah, al;
            wmma::load_matrix_sync(ah, sAh + ks * 16, ASTR);
            wmma::load_matrix_sync(al, sAl + ks * 16, ASTR);
            wmma::fragment<wmma::matrix_b, 16, 16, 16, __nv_bfloat16, wmma::row_major> bh, bl;
            wmma::load_matrix_sync(bh, sBh + ks * 16 * BSTR + wid * 16, BSTR);
            wmma::load_matrix_sync(bl, sBl + ks * 16 * BSTR + wid * 16, BSTR);
            wmma::mma_sync(accH, ah, bh, accH);     // independent chains
            wmma::mma_sync(accL, ah, bl, accL);
            wmma::mma_sync(accL, al, bh, accL);
        }
        __syncthreads();
        if (i + 2 < NCH) { issue(i + 2, i & 1); CP_COMMIT(); }
    }

    // combine split accumulators
#pragma unroll
    for (int e = 0; e < accH.num_elements; e++) accH.x[e] += accL.x[e];

    // ---- store C (reuse stage 0; trailing sync above guarantees drained)
    float* sC = reinterpret_cast<float*>(db);        // [16][CSTR]
    wmma::store_matrix_sync(sC + wid * 16, accH, CSTR, wmma::mem_row_major);
    __syncthreads();

    // ---- fused bias/relu + 128->10 GEMM + log_softmax (warp per 2 rows)
#pragma unroll
    for (int rr = 0; rr < 2; rr++) {
        int r = wid * 2 + rr;
        float hv[4];
#pragma unroll
        for (int j = 0; j < 4; j++) {
            int col = lane + 32 * j;
            float h = sC[r * CSTR + col] + sb1[col];
            hv[j] = h > 0.f ? h : 0.f;
        }
        float lg[10];
#pragma unroll
        for (int qq = 0; qq < 10; qq++) lg[qq] = 0.f;
#pragma unroll
        for (int j = 0; j < 4; j++)
#pragma unroll
            for (int qq = 0; qq < 10; qq++)
                lg[qq] = fmaf(hv[j], sW2t[qq * 128 + lane + 32 * j], lg[qq]);
#pragma unroll
        for (int off = 16; off; off >>= 1)
#pragma unroll
            for (int qq = 0; qq < 10; qq++)
                lg[qq] += __shfl_xor_sync(0xffffffffu, lg[qq], off);

        if (lane == 0) {
            int row = row0 + r;
            if (row < B) {
                float lv[10];
                float m = -1e30f;
#pragma unroll
                for (int qq = 0; qq < 10; qq++) {
                    lv[qq] = lg[qq] + __ldg(&b2[qq]);
                    m = fmaxf(m, lv[qq]);
                }
                float se = 0.f;
#pragma unroll
                for (int qq = 0; qq < 10; qq++) se += expf(lv[qq] - m);
                float lse = m + logf(se);
#pragma unroll
                for (int qq = 0; qq < 10; qq++)
                    out[(size_t)row * 10 + qq] = lv[qq] - lse;
            }
        }
    }
}

// ================================ launch ===================================
extern "C" void kernel_launch(void* const* d_in, const int* in_sizes, int n_in,
                              void* d_out, int out_size) {
    const float* x     = (const float*)d_in[0];   // [B, 784]
    const float* theta = (const float*)d_in[1];   // [2, 4]
    const float* W1    = (const float*)d_in[2];   // [784, 128]
    const float* b1    = (const float*)d_in[3];   // [128]
    const float* W2    = (const float*)d_in[4];   // [128, 10]
    const float* b2    = (const float*)d_in[5];   // [10]
    float* out = (float*)d_out;

    int B = in_sizes[0] / 784;
    if (B > MAX_B) B = MAX_B;

    __nv_bfloat16 *fh, *fl, *wh, *wl;
    cudaGetSymbolAddress((void**)&fh, g_fh);
    cudaGetSymbolAddress((void**)&fl, g_fl);
    cudaGetSymbolAddress((void**)&wh, g_w1h);
    cudaGetSymbolAddress((void**)&wl, g_w1l);

    cudaFuncSetAttribute(gemm_kernel,
                         cudaFuncAttributeMaxDynamicSharedMemorySize, DSMEM_B);

    int qblocks = (B * 196 + 255) / 256;
    quanv_kernel<<<qblocks + 100, 256>>>(x, theta, W1, B, qblocks);

    int mtiles = (B + 15) / 16;
    gemm_kernel<<<mtiles, 256, DSMEM_B>>>(fh, fl, wh, wl, b1, W2, b2, out, B);
}